// round 1
// baseline (speedup 1.0000x reference)
#include <cuda_runtime.h>
#include <math.h>

#define CIN   128
#define COUT  512
#define NMAX  50000
#define EMAX  800000

// ---------------- scratch (static __device__, no runtime alloc) ----------------
__device__ int   g_cnt[NMAX];
__device__ int   g_rowptr[NMAX + 1];
__device__ int   g_cursor[NMAX];
__device__ int   g_col[EMAX];
__device__ float g_sdinv[EMAX];
__device__ float g_dinv[NMAX];
__device__ int   g_bsum[512];
__device__ int   g_is64;
__device__ float g_h0[(size_t)NMAX * CIN];
__device__ float g_h1[(size_t)NMAX * CIN];

// ---------------- int64-vs-int32 edge_index probe ----------------
// If stored as int64 (little-endian), every high 32-bit word is 0 (indices < 2^31).
// If stored as int32, odd 32-bit words are random node ids — nonzero w.h.p.
__global__ void probe_kernel(const unsigned int* p, int n_vals) {
    __shared__ int any;
    int t = threadIdx.x;
    if (t == 0) any = 0;
    __syncthreads();
    int samples = n_vals < 512 ? n_vals : 512;
    for (int i = t; i < samples; i += blockDim.x) {
        if (p[2 * i + 1] != 0u) any = 1;
    }
    __syncthreads();
    if (t == 0) g_is64 = (any == 0) ? 1 : 0;
}

__device__ __forceinline__ int edge_at(const void* ei, long long idx, int is64) {
    return is64 ? (int)((const long long*)ei)[idx] : ((const int*)ei)[idx];
}

// ---------------- degree / norm ----------------
__global__ void zero_cnt_kernel(int N) {
    int i = blockIdx.x * blockDim.x + threadIdx.x;
    if (i < N) g_cnt[i] = 0;
}

__global__ void hist_kernel(const void* ei, int E) {
    int e = blockIdx.x * blockDim.x + threadIdx.x;
    if (e >= E) return;
    int is64 = g_is64;
    int dst = edge_at(ei, (long long)E + e, is64);
    atomicAdd(&g_cnt[dst], 1);
}

__global__ void dinv_kernel(int N) {
    int i = blockIdx.x * blockDim.x + threadIdx.x;
    if (i < N) g_dinv[i] = rsqrtf((float)(g_cnt[i] + 1));  // +1 self-loop; always > 0
}

// ---------------- exclusive scan of g_cnt -> g_rowptr (2-level) ----------------
__global__ void scan1_kernel(int N) {
    __shared__ int sm[256];
    int t = threadIdx.x, i = blockIdx.x * 256 + t;
    int v = (i < N) ? g_cnt[i] : 0;
    sm[t] = v;
    __syncthreads();
    for (int off = 1; off < 256; off <<= 1) {
        int add = (t >= off) ? sm[t - off] : 0;
        __syncthreads();
        sm[t] += add;
        __syncthreads();
    }
    if (i < N) g_rowptr[i] = sm[t] - v;       // exclusive within block
    if (t == 255) g_bsum[blockIdx.x] = sm[255];
}

__global__ void scan2_kernel(int B) {
    __shared__ int sm[512];
    int t = threadIdx.x;
    int v = (t < B) ? g_bsum[t] : 0;
    sm[t] = v;
    __syncthreads();
    for (int off = 1; off < 512; off <<= 1) {
        int add = (t >= off) ? sm[t - off] : 0;
        __syncthreads();
        sm[t] += add;
        __syncthreads();
    }
    if (t < B) g_bsum[t] = sm[t] - v;         // exclusive block offsets
}

__global__ void scan3_kernel(int N) {
    int t = threadIdx.x, i = blockIdx.x * 256 + t;
    if (i < N) {
        int r = g_rowptr[i] + g_bsum[blockIdx.x];
        g_rowptr[i] = r;
        g_cursor[i] = r;
        if (i == N - 1) g_rowptr[N] = r + g_cnt[i];  // == E
    }
}

// ---------------- scatter edges into CSR-by-dst ----------------
__global__ void scatter_kernel(const void* ei, int E) {
    int e = blockIdx.x * blockDim.x + threadIdx.x;
    if (e >= E) return;
    int is64 = g_is64;
    int src = edge_at(ei, e, is64);
    int dst = edge_at(ei, (long long)E + e, is64);
    int pos = atomicAdd(&g_cursor[dst], 1);
    g_col[pos] = src;
    g_sdinv[pos] = g_dinv[src];
}

// ---------------- one propagation hop: warp per dst node, float4/lane ----------------
__global__ void agg_kernel(const float* __restrict__ hin, float* __restrict__ hout, int N) {
    int gt = blockIdx.x * blockDim.x + threadIdx.x;
    int w = gt >> 5;
    int lane = gt & 31;
    if (w >= N) return;
    float dd = g_dinv[w];
    const float4* h4 = (const float4*)hin;
    float4 hv = h4[(size_t)w * 32 + lane];      // self loop
    float s = dd * dd;
    float ax = s * hv.x, ay = s * hv.y, az = s * hv.z, aw = s * hv.w;
    int beg = g_rowptr[w], end = g_rowptr[w + 1];
    for (int e = beg; e < end; e++) {
        int src = g_col[e];                      // warp-broadcast load
        float coef = g_sdinv[e] * dd;            // warp-broadcast load
        float4 v = h4[(size_t)src * 32 + lane];  // 512B gathered row (L2)
        ax += coef * v.x; ay += coef * v.y; az += coef * v.z; aw += coef * v.w;
    }
    float4 o; o.x = ax; o.y = ay; o.z = az; o.w = aw;
    ((float4*)hout)[(size_t)w * 32 + lane] = o;  // coalesced
}

// ---------------- GEMM: out[N,512] = h[N,128] @ W[512,128]^T + b, LeakyReLU(0.1) ----------------
// Block tile: 32 nodes x 64 outs (looped over 8 out-tiles). 256 threads:
//   out_local = t & 63 (coalesced writes), ngrp = t >> 6, 8 nodes/thread.
// ws padded stride 132 floats -> conflict-free LDS.128 across lanes; hs loads warp-broadcast.
__global__ void gemm_kernel(const float* __restrict__ h, const float* __restrict__ W,
                            const float* __restrict__ bias, float* __restrict__ out, int N) {
    extern __shared__ float sm[];
    float* ws = sm;                 // 64 * 132
    float* hs = sm + 64 * 132;      // 32 * 128
    const int t = threadIdx.x;
    const int node0 = blockIdx.x * 32;

    for (int i = t * 4; i < 32 * CIN; i += 256 * 4) {
        int node = i / CIN, c = i % CIN;
        int gn = node0 + node;
        float4 v = make_float4(0.f, 0.f, 0.f, 0.f);
        if (gn < N) v = *(const float4*)(h + (size_t)gn * CIN + c);
        *(float4*)(hs + node * CIN + c) = v;
    }

    const int out_local = t & 63;
    const int ngrp = t >> 6;

    for (int ot = 0; ot < COUT / 64; ot++) {
        __syncthreads();  // hs ready (ot=0) / prev iter done reading ws
        for (int i = t * 4; i < 64 * CIN; i += 256 * 4) {
            int o = i / CIN, c = i % CIN;
            *(float4*)(ws + o * 132 + c) =
                *(const float4*)(W + (size_t)(ot * 64 + o) * CIN + c);
        }
        __syncthreads();

        float acc[8];
        #pragma unroll
        for (int j = 0; j < 8; j++) acc[j] = 0.f;
        const float* wrow = ws + out_local * 132;
        #pragma unroll 4
        for (int c = 0; c < CIN; c += 4) {
            float4 wv = *(const float4*)(wrow + c);
            #pragma unroll
            for (int j = 0; j < 8; j++) {
                float4 hv = *(const float4*)(hs + (ngrp * 8 + j) * CIN + c);
                acc[j] += hv.x * wv.x + hv.y * wv.y + hv.z * wv.z + hv.w * wv.w;
            }
        }

        int og = ot * 64 + out_local;
        float bb = bias[og];
        #pragma unroll
        for (int j = 0; j < 8; j++) {
            int gn = node0 + ngrp * 8 + j;
            if (gn < N) {
                float y = acc[j] + bb;
                out[(size_t)gn * COUT + og] = (y >= 0.f) ? y : 0.1f * y;
            }
        }
    }
}

static const int GEMM_SMEM = (64 * 132 + 32 * CIN) * (int)sizeof(float);  // 50176 B

extern "C" void kernel_launch(void* const* d_in, const int* in_sizes, int n_in,
                              void* d_out, int out_size) {
    const float* x  = (const float*)d_in[0];
    const void*  ei = d_in[1];                 // int64 or int32, probed on device
    const float* W  = (const float*)d_in[2];
    const float* b  = (const float*)d_in[3];
    float* out = (float*)d_out;

    int N = in_sizes[0] / CIN;
    int E = in_sizes[1] / 2;

    void *h0p = nullptr, *h1p = nullptr;
    cudaGetSymbolAddress(&h0p, g_h0);
    cudaGetSymbolAddress(&h1p, g_h1);

    int nbN = (N + 255) / 256;
    int nbE = (E + 255) / 256;

    probe_kernel<<<1, 256>>>((const unsigned int*)ei, 2 * E);
    zero_cnt_kernel<<<nbN, 256>>>(N);
    hist_kernel<<<nbE, 256>>>(ei, E);
    dinv_kernel<<<nbN, 256>>>(N);

    int SB = (N + 255) / 256;   // <= 512 for N <= 131072
    scan1_kernel<<<SB, 256>>>(N);
    scan2_kernel<<<1, 512>>>(SB);
    scan3_kernel<<<SB, 256>>>(N);
    scatter_kernel<<<nbE, 256>>>(ei, E);

    int ab = (N * 32 + 255) / 256;
    agg_kernel<<<ab, 256>>>(x, (float*)h0p, N);
    agg_kernel<<<ab, 256>>>((const float*)h0p, (float*)h1p, N);

    cudaFuncSetAttribute(gemm_kernel, cudaFuncAttributeMaxDynamicSharedMemorySize, GEMM_SMEM);
    gemm_kernel<<<(N + 31) / 32, 256, GEMM_SMEM>>>((const float*)h1p, W, b, out, N);
}

// round 3
// speedup vs baseline: 1.6425x; 1.6425x over previous
#include <cuda_runtime.h>
#include <cuda_bf16.h>
#include <math.h>
#include <stdint.h>

#define CIN   128
#define COUT  512
#define NMAX  50000
#define EMAX  800000

// ---------------- scratch (static __device__, no runtime alloc) ----------------
__device__ int   g_cnt[NMAX];
__device__ int   g_rowptr[NMAX + 1];
__device__ int   g_cursor[NMAX];
__device__ int   g_col[EMAX];
__device__ float g_sdinv[EMAX];
__device__ float g_dinv[NMAX];
__device__ int   g_bsum[512];
__device__ int   g_is64;
__device__ float g_h0[(size_t)NMAX * CIN];
__device__ float g_h1[(size_t)NMAX * CIN];

// ======================= helpers =======================
__device__ __forceinline__ uint32_t smem_to_u32(const void* p) {
    uint32_t a;
    asm("{ .reg .u64 t; cvta.to.shared.u64 t, %1; cvt.u32.u64 %0, t; }" : "=r"(a) : "l"(p));
    return a;
}
__device__ __forceinline__ unsigned short bfbits(float v) {
    __nv_bfloat16 b = __float2bfloat16(v);
    return *reinterpret_cast<unsigned short*>(&b);
}
__device__ __forceinline__ float bfval(unsigned short u) {
    __nv_bfloat16 b = *reinterpret_cast<__nv_bfloat16*>(&u);
    return __bfloat162float(b);
}
__device__ __forceinline__ void ldm4(uint32_t* r, uint32_t addr) {
    asm volatile("ldmatrix.sync.aligned.m8n8.x4.shared.b16 {%0,%1,%2,%3}, [%4];"
                 : "=r"(r[0]), "=r"(r[1]), "=r"(r[2]), "=r"(r[3]) : "r"(addr));
}
__device__ __forceinline__ void mma16816(float* d, const uint32_t* a, const uint32_t* b) {
    asm volatile(
        "mma.sync.aligned.m16n8k16.row.col.f32.bf16.bf16.f32 "
        "{%0,%1,%2,%3}, {%4,%5,%6,%7}, {%8,%9}, {%0,%1,%2,%3};"
        : "+f"(d[0]), "+f"(d[1]), "+f"(d[2]), "+f"(d[3])
        : "r"(a[0]), "r"(a[1]), "r"(a[2]), "r"(a[3]), "r"(b[0]), "r"(b[1]));
}

// ---------------- int64-vs-int32 edge_index probe ----------------
__global__ void probe_kernel(const unsigned int* p, int n_vals) {
    __shared__ int any;
    int t = threadIdx.x;
    if (t == 0) any = 0;
    __syncthreads();
    int samples = n_vals < 512 ? n_vals : 512;
    for (int i = t; i < samples; i += blockDim.x)
        if (p[2 * i + 1] != 0u) any = 1;
    __syncthreads();
    if (t == 0) g_is64 = (any == 0) ? 1 : 0;
}
__device__ __forceinline__ int edge_at(const void* ei, long long idx, int is64) {
    return is64 ? (int)((const long long*)ei)[idx] : ((const int*)ei)[idx];
}

// ---------------- degree / norm / scan / scatter ----------------
__global__ void zero_cnt_kernel(int N) {
    int i = blockIdx.x * blockDim.x + threadIdx.x;
    if (i < N) g_cnt[i] = 0;
}
__global__ void hist_kernel(const void* ei, int E) {
    int e = blockIdx.x * blockDim.x + threadIdx.x;
    if (e >= E) return;
    int dst = edge_at(ei, (long long)E + e, g_is64);
    atomicAdd(&g_cnt[dst], 1);
}
__global__ void dinv_kernel(int N) {
    int i = blockIdx.x * blockDim.x + threadIdx.x;
    if (i < N) g_dinv[i] = rsqrtf((float)(g_cnt[i] + 1));
}
__global__ void scan1_kernel(int N) {
    __shared__ int sm[256];
    int t = threadIdx.x, i = blockIdx.x * 256 + t;
    int v = (i < N) ? g_cnt[i] : 0;
    sm[t] = v;
    __syncthreads();
    for (int off = 1; off < 256; off <<= 1) {
        int add = (t >= off) ? sm[t - off] : 0;
        __syncthreads();
        sm[t] += add;
        __syncthreads();
    }
    if (i < N) g_rowptr[i] = sm[t] - v;
    if (t == 255) g_bsum[blockIdx.x] = sm[255];
}
__global__ void scan2_kernel(int B) {
    __shared__ int sm[512];
    int t = threadIdx.x;
    int v = (t < B) ? g_bsum[t] : 0;
    sm[t] = v;
    __syncthreads();
    for (int off = 1; off < 512; off <<= 1) {
        int add = (t >= off) ? sm[t - off] : 0;
        __syncthreads();
        sm[t] += add;
        __syncthreads();
    }
    if (t < B) g_bsum[t] = sm[t] - v;
}
__global__ void scan3_kernel(int N) {
    int t = threadIdx.x, i = blockIdx.x * 256 + t;
    if (i < N) {
        int r = g_rowptr[i] + g_bsum[blockIdx.x];
        g_rowptr[i] = r;
        g_cursor[i] = r;
        if (i == N - 1) g_rowptr[N] = r + g_cnt[i];
    }
}
__global__ void scatter_kernel(const void* ei, int E) {
    int e = blockIdx.x * blockDim.x + threadIdx.x;
    if (e >= E) return;
    int is64 = g_is64;
    int src = edge_at(ei, e, is64);
    int dst = edge_at(ei, (long long)E + e, is64);
    int pos = atomicAdd(&g_cursor[dst], 1);
    g_col[pos] = src;
    g_sdinv[pos] = g_dinv[src];
}

// ---------------- one propagation hop: warp per dst node ----------------
__global__ void agg_kernel(const float* __restrict__ hin, float* __restrict__ hout, int N) {
    int gt = blockIdx.x * blockDim.x + threadIdx.x;
    int w = gt >> 5;
    int lane = gt & 31;
    if (w >= N) return;
    float dd = g_dinv[w];
    const float4* h4 = (const float4*)hin;
    float4 hv = h4[(size_t)w * 32 + lane];
    float s = dd * dd;
    float ax = s * hv.x, ay = s * hv.y, az = s * hv.z, aw = s * hv.w;
    int beg = g_rowptr[w], end = g_rowptr[w + 1];
    for (int e = beg; e < end; e++) {
        int src = g_col[e];
        float coef = g_sdinv[e] * dd;
        float4 v = h4[(size_t)src * 32 + lane];
        ax += coef * v.x; ay += coef * v.y; az += coef * v.z; aw += coef * v.w;
    }
    float4 o; o.x = ax; o.y = ay; o.z = az; o.w = aw;
    ((float4*)hout)[(size_t)w * 32 + lane] = o;
}

// ---------------- mma.sync GEMM: out[N,512] = h[N,128] @ W^T + b, LeakyReLU ----------------
// CTA: 128 nodes x 128 cols, whole K=128 in smem. bf16 2-term split, 3 passes (hh, hl, lh).
// smem tiles padded to 272B row stride -> conflict-free ldmatrix.x4.
#define STRIDE_B 272
#define OFF_AHI  0
#define OFF_ALO  34816
#define OFF_BHI  69632
#define OFF_BLO  104448
#define MM_SMEM  139264

__global__ __launch_bounds__(256) void mm_kernel(
    const float* __restrict__ h, const float* __restrict__ W,
    const float* __restrict__ bias, float* __restrict__ out, int N)
{
    extern __shared__ char smem[];
    const int tid = threadIdx.x;
    const int node0 = blockIdx.x * 128;
    const int col0 = blockIdx.y * 128;

    // Load + split + store A (h tile) and B (W tile): 128 rows x 32 float4 each.
    for (int i = tid; i < 4096; i += 256) {
        int row = i >> 5, q = i & 31;
        // A
        int gn = node0 + row;
        float4 v = make_float4(0.f, 0.f, 0.f, 0.f);
        if (gn < N) v = *(const float4*)(h + (size_t)gn * CIN + q * 4);
        unsigned short h0 = bfbits(v.x), h1 = bfbits(v.y), h2 = bfbits(v.z), h3 = bfbits(v.w);
        unsigned short l0 = bfbits(v.x - bfval(h0)), l1 = bfbits(v.y - bfval(h1));
        unsigned short l2 = bfbits(v.z - bfval(h2)), l3 = bfbits(v.w - bfval(h3));
        uint2 hp, lp;
        hp.x = (uint32_t)h0 | ((uint32_t)h1 << 16); hp.y = (uint32_t)h2 | ((uint32_t)h3 << 16);
        lp.x = (uint32_t)l0 | ((uint32_t)l1 << 16); lp.y = (uint32_t)l2 | ((uint32_t)l3 << 16);
        *(uint2*)(smem + OFF_AHI + row * STRIDE_B + q * 8) = hp;
        *(uint2*)(smem + OFF_ALO + row * STRIDE_B + q * 8) = lp;
        // B
        float4 w = *(const float4*)(W + (size_t)(col0 + row) * CIN + q * 4);
        unsigned short w0 = bfbits(w.x), w1 = bfbits(w.y), w2 = bfbits(w.z), w3 = bfbits(w.w);
        unsigned short m0_ = bfbits(w.x - bfval(w0)), m1 = bfbits(w.y - bfval(w1));
        unsigned short m2 = bfbits(w.z - bfval(w2)), m3 = bfbits(w.w - bfval(w3));
        uint2 wp, mp;
        wp.x = (uint32_t)w0 | ((uint32_t)w1 << 16); wp.y = (uint32_t)w2 | ((uint32_t)w3 << 16);
        mp.x = (uint32_t)m0_ | ((uint32_t)m1 << 16); mp.y = (uint32_t)m2 | ((uint32_t)m3 << 16);
        *(uint2*)(smem + OFF_BHI + row * STRIDE_B + q * 8) = wp;
        *(uint2*)(smem + OFF_BLO + row * STRIDE_B + q * 8) = mp;
    }
    __syncthreads();

    const int lane = tid & 31, wid = tid >> 5;
    const int m0 = (wid & 3) * 32;          // 4 warps along M
    const int n0 = (wid >> 2) * 64;         // 2 warps along N
    const uint32_t sb = smem_to_u32(smem);

    // per-lane ldmatrix addresses (byte offsets within a tile)
    const uint32_t aoff = (uint32_t)(m0 + (lane & 15)) * STRIDE_B + ((lane >> 4) << 4);
    const uint32_t boff = (uint32_t)(n0 + ((lane >> 4) << 3) + (lane & 7)) * STRIDE_B
                        + (((lane >> 3) & 1) << 4);

    float acc[2][8][4];
    #pragma unroll
    for (int a = 0; a < 2; a++)
        #pragma unroll
        for (int b = 0; b < 8; b++)
            #pragma unroll
            for (int c = 0; c < 4; c++) acc[a][b][c] = 0.f;

    for (int pass = 0; pass < 3; pass++) {
        uint32_t aB = sb + (pass == 2 ? OFF_ALO : OFF_AHI) + aoff;
        uint32_t bB = sb + (pass == 1 ? OFF_BLO : OFF_BHI) + boff;
        #pragma unroll
        for (int ks = 0; ks < 8; ks++) {
            uint32_t aF[2][4], bF[4][4];
            ldm4(aF[0], aB + ks * 32);
            ldm4(aF[1], aB + 16 * STRIDE_B + ks * 32);
            #pragma unroll
            for (int g4 = 0; g4 < 4; g4++)
                ldm4(bF[g4], bB + g4 * 16 * STRIDE_B + ks * 32);
            #pragma unroll
            for (int mt = 0; mt < 2; mt++)
                #pragma unroll
                for (int g4 = 0; g4 < 4; g4++) {
                    mma16816(acc[mt][2 * g4],     aF[mt], bF[g4]);
                    mma16816(acc[mt][2 * g4 + 1], aF[mt], bF[g4] + 2);
                }
        }
    }

    // epilogue: bias + LeakyReLU + store
    const int g = lane >> 2, tg = lane & 3;
    #pragma unroll
    for (int ng = 0; ng < 8; ng++) {
        int col = col0 + n0 + ng * 8 + tg * 2;
        float2 bb = *(const float2*)(bias + col);
        #pragma unroll
        for (int mt = 0; mt < 2; mt++) {
            int r0 = node0 + m0 + mt * 16 + g;
            if (r0 < N) {
                float y0 = acc[mt][ng][0] + bb.x;
                float y1 = acc[mt][ng][1] + bb.y;
                float2 o;
                o.x = (y0 >= 0.f) ? y0 : 0.1f * y0;
                o.y = (y1 >= 0.f) ? y1 : 0.1f * y1;
                *(float2*)(out + (size_t)r0 * COUT + col) = o;
            }
            int r1 = r0 + 8;
            if (r1 < N) {
                float y2 = acc[mt][ng][2] + bb.x;
                float y3 = acc[mt][ng][3] + bb.y;
                float2 o;
                o.x = (y2 >= 0.f) ? y2 : 0.1f * y2;
                o.y = (y3 >= 0.f) ? y3 : 0.1f * y3;
                *(float2*)(out + (size_t)r1 * COUT + col) = o;
            }
        }
    }
}

extern "C" void kernel_launch(void* const* d_in, const int* in_sizes, int n_in,
                              void* d_out, int out_size) {
    const float* x  = (const float*)d_in[0];
    const void*  ei = d_in[1];
    const float* W  = (const float*)d_in[2];
    const float* b  = (const float*)d_in[3];
    float* out = (float*)d_out;

    int N = in_sizes[0] / CIN;
    int E = in_sizes[1] / 2;

    void *h0p = nullptr, *h1p = nullptr;
    cudaGetSymbolAddress(&h0p, g_h0);
    cudaGetSymbolAddress(&h1p, g_h1);

    int nbN = (N + 255) / 256;
    int nbE = (E + 255) / 256;

    probe_kernel<<<1, 256>>>((const unsigned int*)ei, 2 * E);
    zero_cnt_kernel<<<nbN, 256>>>(N);
    hist_kernel<<<nbE, 256>>>(ei, E);
    dinv_kernel<<<nbN, 256>>>(N);

    int SB = (N + 255) / 256;
    scan1_kernel<<<SB, 256>>>(N);
    scan2_kernel<<<1, 512>>>(SB);
    scan3_kernel<<<SB, 256>>>(N);
    scatter_kernel<<<nbE, 256>>>(ei, E);

    int ab = (N * 32 + 255) / 256;
    agg_kernel<<<ab, 256>>>(x, (float*)h0p, N);
    agg_kernel<<<ab, 256>>>((const float*)h0p, (float*)h1p, N);

    cudaFuncSetAttribute(mm_kernel, cudaFuncAttributeMaxDynamicSharedMemorySize, MM_SMEM);
    dim3 grid((N + 127) / 128, COUT / 128);
    mm_kernel<<<grid, 256, MM_SMEM>>>((const float*)h1p, W, b, out, N);
}

// round 4
// speedup vs baseline: 1.9096x; 1.1626x over previous
#include <cuda_runtime.h>
#include <cuda_bf16.h>
#include <math.h>
#include <stdint.h>

#define CIN   128
#define COUT  512
#define NMAX  50000
#define EMAX  800000

// ---------------- scratch (static __device__, no runtime alloc) ----------------
__device__ int   g_cnt[NMAX];
__device__ int   g_rowptr[NMAX + 1];
__device__ int   g_cursor[NMAX];
__device__ int2  g_rec[EMAX];              // {src, bits(dinv[src])}
__device__ float g_dinv[NMAX];
__device__ int   g_bsum[512];
__device__ int   g_is64;
__device__ float g_h0[(size_t)NMAX * CIN];
__device__ unsigned short g_h1hi[(size_t)NMAX * CIN];
__device__ unsigned short g_h1lo[(size_t)NMAX * CIN];
__device__ unsigned short g_whi[COUT * CIN];
__device__ unsigned short g_wlo[COUT * CIN];

// ======================= helpers =======================
__device__ __forceinline__ uint32_t smem_to_u32(const void* p) {
    uint32_t a;
    asm("{ .reg .u64 t; cvta.to.shared.u64 t, %1; cvt.u32.u64 %0, t; }" : "=r"(a) : "l"(p));
    return a;
}
__device__ __forceinline__ unsigned short bfbits(float v) {
    __nv_bfloat16 b = __float2bfloat16(v);
    return *reinterpret_cast<unsigned short*>(&b);
}
__device__ __forceinline__ float bfval(unsigned short u) {
    __nv_bfloat16 b = *reinterpret_cast<__nv_bfloat16*>(&u);
    return __bfloat162float(b);
}
__device__ __forceinline__ void ldm4(uint32_t* r, uint32_t addr) {
    asm volatile("ldmatrix.sync.aligned.m8n8.x4.shared.b16 {%0,%1,%2,%3}, [%4];"
                 : "=r"(r[0]), "=r"(r[1]), "=r"(r[2]), "=r"(r[3]) : "r"(addr));
}
__device__ __forceinline__ void mma16816(float* d, const uint32_t* a, const uint32_t* b) {
    asm volatile(
        "mma.sync.aligned.m16n8k16.row.col.f32.bf16.bf16.f32 "
        "{%0,%1,%2,%3}, {%4,%5,%6,%7}, {%8,%9}, {%0,%1,%2,%3};"
        : "+f"(d[0]), "+f"(d[1]), "+f"(d[2]), "+f"(d[3])
        : "r"(a[0]), "r"(a[1]), "r"(a[2]), "r"(a[3]), "r"(b[0]), "r"(b[1]));
}
__device__ __forceinline__ int edge_at(const void* ei, long long idx, int is64) {
    return is64 ? (int)((const long long*)ei)[idx] : ((const int*)ei)[idx];
}

// ---------------- K1: zero counters + dtype probe (block 0) ----------------
__global__ void init_kernel(const unsigned int* p, int n_vals, int N) {
    int i = blockIdx.x * blockDim.x + threadIdx.x;
    if (i < N) g_cnt[i] = 0;
    if (blockIdx.x == 0) {
        __shared__ int any;
        int t = threadIdx.x;
        if (t == 0) any = 0;
        __syncthreads();
        int samples = n_vals < 512 ? n_vals : 512;
        for (int j = t; j < samples; j += blockDim.x)
            if (p[2 * j + 1] != 0u) any = 1;
        __syncthreads();
        if (t == 0) g_is64 = (any == 0) ? 1 : 0;
    }
}

// ---------------- K2: degree histogram ----------------
__global__ void hist_kernel(const void* ei, int E) {
    int e = blockIdx.x * blockDim.x + threadIdx.x;
    if (e >= E) return;
    int dst = edge_at(ei, (long long)E + e, g_is64);
    atomicAdd(&g_cnt[dst], 1);
}

// ---------------- K3: per-block scan + block sums + dinv ----------------
__global__ void scan1_kernel(int N) {
    __shared__ int sm[256];
    int t = threadIdx.x, i = blockIdx.x * 256 + t;
    int v = (i < N) ? g_cnt[i] : 0;
    sm[t] = v;
    __syncthreads();
    for (int off = 1; off < 256; off <<= 1) {
        int add = (t >= off) ? sm[t - off] : 0;
        __syncthreads();
        sm[t] += add;
        __syncthreads();
    }
    if (i < N) {
        g_rowptr[i] = sm[t] - v;
        g_dinv[i] = rsqrtf((float)(v + 1));
    }
    if (t == 255) g_bsum[blockIdx.x] = sm[255];
}

// ---------------- K4: add block-sum prefix (re-reduced per block) ----------------
__global__ void scan3_kernel(int N) {
    __shared__ int red[256];
    int t = threadIdx.x, bid = blockIdx.x;
    int acc = 0;
    for (int j = t; j < bid; j += 256) acc += g_bsum[j];
    red[t] = acc;
    __syncthreads();
    for (int off = 128; off > 0; off >>= 1) {
        if (t < off) red[t] += red[t + off];
        __syncthreads();
    }
    int base = red[0];
    int i = bid * 256 + t;
    if (i < N) {
        int r = g_rowptr[i] + base;
        g_rowptr[i] = r;
        g_cursor[i] = r;
        if (i == N - 1) g_rowptr[N] = r + g_cnt[i];
    }
}

// ---------------- K5: scatter edges into CSR records ----------------
__global__ void scatter_kernel(const void* ei, int E) {
    int e = blockIdx.x * blockDim.x + threadIdx.x;
    if (e >= E) return;
    int is64 = g_is64;
    int src = edge_at(ei, e, is64);
    int dst = edge_at(ei, (long long)E + e, is64);
    int pos = atomicAdd(&g_cursor[dst], 1);
    int2 r;
    r.x = src;
    r.y = __float_as_int(g_dinv[src]);
    g_rec[pos] = r;
}

// ---------------- K6: W -> bf16 hi/lo split ----------------
__global__ void wprep_kernel(const float* __restrict__ W) {
    int i = blockIdx.x * blockDim.x + threadIdx.x;    // 0 .. 512*32-1
    if (i >= COUT * CIN / 4) return;
    float4 v = ((const float4*)W)[i];
    unsigned short h0 = bfbits(v.x), h1 = bfbits(v.y), h2 = bfbits(v.z), h3 = bfbits(v.w);
    unsigned short l0 = bfbits(v.x - bfval(h0)), l1 = bfbits(v.y - bfval(h1));
    unsigned short l2 = bfbits(v.z - bfval(h2)), l3 = bfbits(v.w - bfval(h3));
    uint2 hp, lp;
    hp.x = (uint32_t)h0 | ((uint32_t)h1 << 16); hp.y = (uint32_t)h2 | ((uint32_t)h3 << 16);
    lp.x = (uint32_t)l0 | ((uint32_t)l1 << 16); lp.y = (uint32_t)l2 | ((uint32_t)l3 << 16);
    ((uint2*)g_whi)[i] = hp;
    ((uint2*)g_wlo)[i] = lp;
}

// ---------------- aggregation inner (warp per dst, unroll x2) ----------------
__device__ __forceinline__ float4 agg_row(const float4* __restrict__ h4, int w, int lane) {
    float dd = g_dinv[w];
    float4 hv = h4[(size_t)w * 32 + lane];
    float s = dd * dd;
    float ax = s * hv.x, ay = s * hv.y, az = s * hv.z, aw = s * hv.w;
    float bx = 0.f, by = 0.f, bz = 0.f, bw = 0.f;
    int e = g_rowptr[w], end = g_rowptr[w + 1];
    for (; e + 2 <= end; e += 2) {
        int2 r0 = g_rec[e], r1 = g_rec[e + 1];
        float c0 = __int_as_float(r0.y) * dd;
        float c1 = __int_as_float(r1.y) * dd;
        float4 v0 = h4[(size_t)r0.x * 32 + lane];
        float4 v1 = h4[(size_t)r1.x * 32 + lane];
        ax += c0 * v0.x; ay += c0 * v0.y; az += c0 * v0.z; aw += c0 * v0.w;
        bx += c1 * v1.x; by += c1 * v1.y; bz += c1 * v1.z; bw += c1 * v1.w;
    }
    if (e < end) {
        int2 r0 = g_rec[e];
        float c0 = __int_as_float(r0.y) * dd;
        float4 v0 = h4[(size_t)r0.x * 32 + lane];
        ax += c0 * v0.x; ay += c0 * v0.y; az += c0 * v0.z; aw += c0 * v0.w;
    }
    float4 o;
    o.x = ax + bx; o.y = ay + by; o.z = az + bz; o.w = aw + bw;
    return o;
}

// K7: hop 1 -> f32
__global__ void agg_kernel(const float* __restrict__ hin, float* __restrict__ hout, int N) {
    int gt = blockIdx.x * blockDim.x + threadIdx.x;
    int w = gt >> 5, lane = gt & 31;
    if (w >= N) return;
    float4 o = agg_row((const float4*)hin, w, lane);
    ((float4*)hout)[(size_t)w * 32 + lane] = o;
}

// K8: hop 2 -> pre-split bf16 hi/lo
__global__ void agg_split_kernel(const float* __restrict__ hin, int N) {
    int gt = blockIdx.x * blockDim.x + threadIdx.x;
    int w = gt >> 5, lane = gt & 31;
    if (w >= N) return;
    float4 o = agg_row((const float4*)hin, w, lane);
    unsigned short h0 = bfbits(o.x), h1 = bfbits(o.y), h2 = bfbits(o.z), h3 = bfbits(o.w);
    unsigned short l0 = bfbits(o.x - bfval(h0)), l1 = bfbits(o.y - bfval(h1));
    unsigned short l2 = bfbits(o.z - bfval(h2)), l3 = bfbits(o.w - bfval(h3));
    uint2 hp, lp;
    hp.x = (uint32_t)h0 | ((uint32_t)h1 << 16); hp.y = (uint32_t)h2 | ((uint32_t)h3 << 16);
    lp.x = (uint32_t)l0 | ((uint32_t)l1 << 16); lp.y = (uint32_t)l2 | ((uint32_t)l3 << 16);
    ((uint2*)g_h1hi)[(size_t)w * 32 + lane] = hp;
    ((uint2*)g_h1lo)[(size_t)w * 32 + lane] = lp;
}

// ---------------- K9: mma.sync GEMM (pre-split inputs, copy-only load phase) ----------------
#define STRIDE_B 272
#define OFF_AHI  0
#define OFF_ALO  34816
#define OFF_BHI  69632
#define OFF_BLO  104448
#define MM_SMEM  139264

__global__ __launch_bounds__(256) void mm_kernel(
    const float* __restrict__ bias, float* __restrict__ out, int N)
{
    extern __shared__ char smem[];
    const int tid = threadIdx.x;
    const int node0 = blockIdx.x * 128;
    const int col0 = blockIdx.y * 128;

    const uint4* hhi = (const uint4*)g_h1hi;
    const uint4* hlo = (const uint4*)g_h1lo;
    const uint4* whi = (const uint4*)g_whi;
    const uint4* wlo = (const uint4*)g_wlo;

    // copy 4 pre-split 32KB tiles into padded smem (8 uint4 per tile per thread)
    for (int i = tid; i < 2048; i += 256) {
        int row = i >> 4, q = i & 15;
        int gn = node0 + row;
        uint4 z = make_uint4(0u, 0u, 0u, 0u);
        uint4 ah = (gn < N) ? hhi[(size_t)gn * 16 + q] : z;
        uint4 al = (gn < N) ? hlo[(size_t)gn * 16 + q] : z;
        *(uint4*)(smem + OFF_AHI + row * STRIDE_B + q * 16) = ah;
        *(uint4*)(smem + OFF_ALO + row * STRIDE_B + q * 16) = al;
        uint4 bh = whi[(size_t)(col0 + row) * 16 + q];
        uint4 bl = wlo[(size_t)(col0 + row) * 16 + q];
        *(uint4*)(smem + OFF_BHI + row * STRIDE_B + q * 16) = bh;
        *(uint4*)(smem + OFF_BLO + row * STRIDE_B + q * 16) = bl;
    }
    __syncthreads();

    const int lane = tid & 31, wid = tid >> 5;
    const int m0 = (wid & 3) * 32;
    const int n0 = (wid >> 2) * 64;
    const uint32_t sb = smem_to_u32(smem);

    const uint32_t aoff = (uint32_t)(m0 + (lane & 15)) * STRIDE_B + ((lane >> 4) << 4);
    const uint32_t boff = (uint32_t)(n0 + ((lane >> 4) << 3) + (lane & 7)) * STRIDE_B
                        + (((lane >> 3) & 1) << 4);

    float acc[2][8][4];
    #pragma unroll
    for (int a = 0; a < 2; a++)
        #pragma unroll
        for (int b = 0; b < 8; b++)
            #pragma unroll
            for (int c = 0; c < 4; c++) acc[a][b][c] = 0.f;

    for (int pass = 0; pass < 3; pass++) {
        uint32_t aB = sb + (pass == 2 ? OFF_ALO : OFF_AHI) + aoff;
        uint32_t bB = sb + (pass == 1 ? OFF_BLO : OFF_BHI) + boff;
        #pragma unroll
        for (int ks = 0; ks < 8; ks++) {
            uint32_t aF[2][4], bF[4][4];
            ldm4(aF[0], aB + ks * 32);
            ldm4(aF[1], aB + 16 * STRIDE_B + ks * 32);
            #pragma unroll
            for (int g4 = 0; g4 < 4; g4++)
                ldm4(bF[g4], bB + g4 * 16 * STRIDE_B + ks * 32);
            #pragma unroll
            for (int mt = 0; mt < 2; mt++)
                #pragma unroll
                for (int g4 = 0; g4 < 4; g4++) {
                    mma16816(acc[mt][2 * g4],     aF[mt], bF[g4]);
                    mma16816(acc[mt][2 * g4 + 1], aF[mt], bF[g4] + 2);
                }
        }
    }

    const int g = lane >> 2, tg = lane & 3;
    #pragma unroll
    for (int ng = 0; ng < 8; ng++) {
        int col = col0 + n0 + ng * 8 + tg * 2;
        float2 bb = *(const float2*)(bias + col);
        #pragma unroll
        for (int mt = 0; mt < 2; mt++) {
            int r0 = node0 + m0 + mt * 16 + g;
            if (r0 < N) {
                float y0 = acc[mt][ng][0] + bb.x;
                float y1 = acc[mt][ng][1] + bb.y;
                float2 o;
                o.x = (y0 >= 0.f) ? y0 : 0.1f * y0;
                o.y = (y1 >= 0.f) ? y1 : 0.1f * y1;
                *(float2*)(out + (size_t)r0 * COUT + col) = o;
            }
            int r1 = r0 + 8;
            if (r1 < N) {
                float y2 = acc[mt][ng][2] + bb.x;
                float y3 = acc[mt][ng][3] + bb.y;
                float2 o;
                o.x = (y2 >= 0.f) ? y2 : 0.1f * y2;
                o.y = (y3 >= 0.f) ? y3 : 0.1f * y3;
                *(float2*)(out + (size_t)r1 * COUT + col) = o;
            }
        }
    }
}

extern "C" void kernel_launch(void* const* d_in, const int* in_sizes, int n_in,
                              void* d_out, int out_size) {
    const float* x  = (const float*)d_in[0];
    const void*  ei = d_in[1];
    const float* W  = (const float*)d_in[2];
    const float* b  = (const float*)d_in[3];
    float* out = (float*)d_out;

    int N = in_sizes[0] / CIN;
    int E = in_sizes[1] / 2;

    void* h0p = nullptr;
    cudaGetSymbolAddress(&h0p, g_h0);

    int nbN = (N + 255) / 256;
    int nbE = (E + 255) / 256;

    init_kernel<<<nbN, 256>>>((const unsigned int*)ei, 2 * E, N);
    hist_kernel<<<nbE, 256>>>(ei, E);
    scan1_kernel<<<nbN, 256>>>(N);
    scan3_kernel<<<nbN, 256>>>(N);
    scatter_kernel<<<nbE, 256>>>(ei, E);
    wprep_kernel<<<(COUT * CIN / 4 + 255) / 256, 256>>>(W);

    int ab = (N * 32 + 255) / 256;
    agg_kernel<<<ab, 256>>>(x, (float*)h0p, N);
    agg_split_kernel<<<ab, 256>>>((const float*)h0p, N);

    cudaFuncSetAttribute(mm_kernel, cudaFuncAttributeMaxDynamicSharedMemorySize, MM_SMEM);
    dim3 grid((N + 127) / 128, COUT / 128);
    mm_kernel<<<grid, 256, MM_SMEM>>>(b, out, N);
}